// round 16
// baseline (speedup 1.0000x reference)
#include <cuda_runtime.h>
#include <cuda_fp16.h>
#include <math.h>
#include <stdint.h>

// ---------------- problem constants ----------------
#define RAYS      2048
#define SS        128
#define MH        64               // samples per CTA (half ray)
#define HID       256
#define NTHREADS  256
#define KC        64               // K per weight chunk (fp16)
#define NCHUNK    14               // per MLP: layer0: 2 (Kpad=128), layers1-3: 4 each
#define ASTRIDE   264              // A row stride fp16 (33*16B: conflict-free ldmatrix)
#define BSTRIDE   72               // B row stride fp16 (9*16B: odd -> conflict-free)
#define BBUF      36864            // one B buffer: 256 rows * 144 B

// ---- shared memory byte offsets (total 113664 -> 2 CTAs/SM) ----
#define A_PL      0                              // 64*264*2 = 33792
#define BUFBASE   33792                          // 2 * 36864 = 73728 -> 107520
#define SM_W4     107520                         // 256*5*4 = 5120 -> 112640
#define SM_OUTS   112640                         // 64*4*4 = 1024 -> 113664
#define SM_TOTAL  113664

// Pre-transposed fp16 weight chunk images (full N): [mlp][chunk][256*64]
__device__ __align__(16) __half g_wimg[2][NCHUNK][HID * KC];
// inter-kernel per-sample scratch
__device__ float g_sig[RAYS * SS];
__device__ float g_bw [RAYS * SS];
__device__ float g_rgb[RAYS * SS * 3];

struct MLPParams { const float* W[5]; const float* b[5]; };

// ---------------- PTX helpers (all baseline sm_80 ISA) ----------------
__device__ __forceinline__ uint32_t smem_u32(const void* p) {
    uint32_t a;
    asm("{ .reg .u64 t; cvta.to.shared.u64 t, %1; cvt.u32.u64 %0, t; }" : "=r"(a) : "l"(p));
    return a;
}

#define LDSM4(r0, r1, r2, r3, addr) \
    asm volatile("ldmatrix.sync.aligned.m8n8.x4.shared.b16 {%0,%1,%2,%3}, [%4];" \
        : "=r"(r0), "=r"(r1), "=r"(r2), "=r"(r3) : "r"(addr))

#define MMA16816(c, a0, a1, a2, a3, b0, b1) \
    asm volatile("mma.sync.aligned.m16n8k16.row.col.f32.f16.f16.f32 " \
        "{%0,%1,%2,%3}, {%4,%5,%6,%7}, {%8,%9}, {%0,%1,%2,%3};" \
        : "+f"((c)[0]), "+f"((c)[1]), "+f"((c)[2]), "+f"((c)[3]) \
        : "r"(a0), "r"(a1), "r"(a2), "r"(a3), "r"(b0), "r"(b1))

__device__ __forceinline__ void cp16(uint32_t dst, const void* src) {
    asm volatile("cp.async.cg.shared.global [%0], [%1], 16;" :: "r"(dst), "l"(src));
}
#define CP_COMMIT() asm volatile("cp.async.commit_group;" ::: "memory")
#define CP_WAIT1()  asm volatile("cp.async.wait_group 1;" ::: "memory")
#define CP_WAIT0()  asm volatile("cp.async.wait_group 0;" ::: "memory")

__device__ __forceinline__ float sigmoidf_(float x) { return 1.0f / (1.0f + expf(-x)); }

__device__ __forceinline__ uint32_t pack_h2(float v0, float v1) {
    __half2 h = __floats2half2_rn(v0, v1);
    return *reinterpret_cast<uint32_t*>(&h);
}
__device__ __forceinline__ float2 h2f(uint32_t u) {
    __half2 h = *reinterpret_cast<__half2*>(&u);
    return __half22float2(h);
}

// ---------------- pre-pass: [N=256][Kc=64] fp16 images ----------------
__global__ void prepass_kernel(MLPParams st, MLPParams dy) {
    const int bi  = blockIdx.x;            // 0..27
    const int mlp = bi / NCHUNK;
    const int c   = bi % NCHUNK;
    const int layer = (c < 2) ? 0 : 1 + (c - 2) / 4;
    const int kbase = (c < 2) ? c * KC : ((c - 2) % 4) * KC;
    const float* W = mlp ? dy.W[layer] : st.W[layer];
    const int Kreal = (layer == 0) ? (mlp ? 99 : 90) : HID;

    __half* outH = g_wimg[mlp][c];
    const int n = threadIdx.x;             // 0..255
    for (int k = 0; k < KC; k++) {
        const int kg = kbase + k;
        const float w = (kg < Kreal) ? __ldg(W + (size_t)kg * HID + n) : 0.f;
        outH[n * KC + k] = __float2half_rn(w);
    }
}

// ---- GEMM chunk: warp tile 64(M) x 32(N), Kc=64, LDS/MMA interleaved ----
__device__ __forceinline__ void gemm_chunk(uint32_t aBase, uint32_t bB, float acc[16][4]) {
    uint32_t a[16], b[2][8];
#pragma unroll
    for (int ms = 0; ms < 4; ms++)
        LDSM4(a[ms*4+0], a[ms*4+1], a[ms*4+2], a[ms*4+3],
              aBase + ms * (16 * ASTRIDE * 2));
#pragma unroll
    for (int ns = 0; ns < 2; ns++)
        LDSM4(b[0][ns*4+0], b[0][ns*4+1], b[0][ns*4+2], b[0][ns*4+3],
              bB + ns * (16 * BSTRIDE * 2));
#pragma unroll
    for (int ks = 0; ks < 4; ks++) {
        const int cur = ks & 1, nxt = cur ^ 1;
        if (ks < 3) {
            const uint32_t nbk = bB + (ks + 1) * 32;
#pragma unroll
            for (int ns = 0; ns < 2; ns++)
                LDSM4(b[nxt][ns*4+0], b[nxt][ns*4+1], b[nxt][ns*4+2], b[nxt][ns*4+3],
                      nbk + ns * (16 * BSTRIDE * 2));
        }
#pragma unroll
        for (int ms = 0; ms < 4; ms++) {
            MMA16816(acc[ms*4+0], a[ms*4+0], a[ms*4+1], a[ms*4+2], a[ms*4+3],
                     b[cur][0], b[cur][1]);
            MMA16816(acc[ms*4+1], a[ms*4+0], a[ms*4+1], a[ms*4+2], a[ms*4+3],
                     b[cur][2], b[cur][3]);
            MMA16816(acc[ms*4+2], a[ms*4+0], a[ms*4+1], a[ms*4+2], a[ms*4+3],
                     b[cur][4], b[cur][5]);
            MMA16816(acc[ms*4+3], a[ms*4+0], a[ms*4+1], a[ms*4+2], a[ms*4+3],
                     b[cur][6], b[cur][7]);
            if (ks < 3)
                LDSM4(a[ms*4+0], a[ms*4+1], a[ms*4+2], a[ms*4+3],
                      aBase + (ks + 1) * 32 + ms * (16 * ASTRIDE * 2));
        }
    }
}

// ---------------- kernel 1: MLPs for one half-ray (64 samples) ----------------
__global__ void __launch_bounds__(NTHREADS, 2)
nerf_mlp(const float* __restrict__ pts, const float* __restrict__ dir,
         const float* __restrict__ tim, MLPParams st, MLPParams dy)
{
    extern __shared__ char sm[];
    const uint32_t sbase = smem_u32(sm);

    const int tid  = threadIdx.x;
    const int wid  = tid >> 5;           // 0..7 -> N cols 32*wid
    const int lane = tid & 31;
    const int ray  = blockIdx.x >> 1;
    const int s0   = (blockIdx.x & 1) * MH;

    float* sOutS = (float*)(sm + SM_OUTS);
    float* sW4f  = (float*)(sm + SM_W4);
    const uint32_t bufBase = sbase + BUFBASE;

    // per-thread ldmatrix address components
    const int r8 = lane & 7, g = lane >> 3;
    const uint32_t aRow = (uint32_t)((g & 1) * 8 + r8);
    const uint32_t aOffBase = (aRow * ASTRIDE + (uint32_t)(g >> 1) * 8) * 2;
    const uint32_t bRow = (uint32_t)(wid * 32 + (g >> 1) * 8 + r8);
    const uint32_t bOff = (bRow * BSTRIDE + (g & 1) * 8) * 2;

    const int rowBase = lane >> 2;                    // + 16*ms, +8 for c[2..3]
    const int colBase = wid * 32 + 2 * (lane & 3);    // + 8*nf

    for (int mlp = 0; mlp < 2; mlp++) {
        const float* const* Wp = mlp ? dy.W : st.W;
        const float* const* Bp = mlp ? dy.b : st.b;
        const int n4 = mlp ? 5 : 4;

        CP_WAIT0();
        __syncthreads();       // A plane / buffers free for reuse

        // ---- encode 64 samples into fp16 A plane, 4-way warp-uniform split ----
        {
            const int m = tid & 63;
            const int q = tid >> 6;
            const long base = (long)ray * SS + s0 + m;
            char* arow = sm + A_PL + (size_t)m * (ASTRIDE * 2);
#define STH(col, v) (*(__half*)(arow + (col) * 2) = __float2half_rn(v))
            if (q == 0) {
                const float p0 = pts[base*3+0], p1 = pts[base*3+1], p2 = pts[base*3+2];
                STH(0, p0); STH(1, p1); STH(2, p2);
                float f = 1.f;
#pragma unroll
                for (int l = 0; l < 5; l++) {
                    float c0,sx,c1,sy,c2,sz;
                    sincosf(f*p0,&sx,&c0); sincosf(f*p1,&sy,&c1); sincosf(f*p2,&sz,&c2);
                    const int o = 3 + 6*l;
                    STH(o,sx); STH(o+1,sy); STH(o+2,sz);
                    STH(o+3,c0); STH(o+4,c1); STH(o+5,c2);
                    f *= 2.f;
                }
            } else if (q == 1) {
                const float p0 = pts[base*3+0], p1 = pts[base*3+1], p2 = pts[base*3+2];
                float f = 32.f;
#pragma unroll
                for (int l = 0; l < 5; l++) {
                    float c0,sx,c1,sy,c2,sz;
                    sincosf(f*p0,&sx,&c0); sincosf(f*p1,&sy,&c1); sincosf(f*p2,&sz,&c2);
                    const int o = 33 + 6*l;
                    STH(o,sx); STH(o+1,sy); STH(o+2,sz);
                    STH(o+3,c0); STH(o+4,c1); STH(o+5,c2);
                    f *= 2.f;
                }
            } else if (q == 2) {
                const float d0 = dir[base*3+0], d1 = dir[base*3+1], d2 = dir[base*3+2];
                STH(63, d0); STH(64, d1); STH(65, d2);
                float f = 1.f;
#pragma unroll
                for (int l = 0; l < 4; l++) {
                    float c0,sx,c1,sy,c2,sz;
                    sincosf(f*d0,&sx,&c0); sincosf(f*d1,&sy,&c1); sincosf(f*d2,&sz,&c2);
                    const int o = 66 + 6*l;
                    STH(o,sx); STH(o+1,sy); STH(o+2,sz);
                    STH(o+3,c0); STH(o+4,c1); STH(o+5,c2);
                    f *= 2.f;
                }
            } else {
                const float t = tim[base];
                STH(90, t);
                float f = 1.f;
#pragma unroll
                for (int l = 0; l < 4; l++) {
                    float s, c; sincosf(f*t, &s, &c);
                    STH(91 + 2*l, s); STH(92 + 2*l, c);
                    f *= 2.f;
                }
#pragma unroll
                for (int col = 99; col < 128; col++) STH(col, 0.f);
            }
#undef STH
        }
        __syncthreads();

        // ---- prefetch chunks 0,1 (2048 x 16B per chunk) ----
        int cg = 0;
        for (int pc = 0; pc < 2; pc++) {
            const char* src = (const char*)g_wimg[mlp][pc];
            const uint32_t dstB = bufBase + (uint32_t)pc * BBUF;
#pragma unroll
            for (int i = 0; i < 8; i++) {
                const int idx = tid + i * NTHREADS;              // 0..2047
                const uint32_t d = dstB + (uint32_t)(idx >> 3) * (BSTRIDE * 2) + (idx & 7) * 16;
                cp16(d, src + idx * 16);
            }
            CP_COMMIT();
        }

        for (int layer = 0; layer < 4; layer++) {
            if (layer == 3)
                for (int i = tid; i < HID * n4; i += NTHREADS) sW4f[i] = __ldg(Wp[4] + i);

            float acc[16][4];
#pragma unroll
            for (int a = 0; a < 16; a++)
#pragma unroll
                for (int q = 0; q < 4; q++) acc[a][q] = 0.f;

            const int nch = (layer == 0) ? 2 : 4;
            for (int c = 0; c < nch; c++) {
                CP_WAIT1();                        // chunk cg resident (this thread's share)
                __syncthreads();                   // all threads' shares visible
                const uint32_t bB = bufBase + (uint32_t)(cg & 1) * BBUF + bOff;
                gemm_chunk(sbase + A_PL + aOffBase + c * (KC * 2), bB, acc);
                __syncthreads();                   // done reading buf before overwrite
                if (cg + 2 < NCHUNK) {
                    const char* src = (const char*)g_wimg[mlp][cg + 2];
                    const uint32_t dstB = bufBase + (uint32_t)(cg & 1) * BBUF;
#pragma unroll
                    for (int i = 0; i < 8; i++) {
                        const int idx = tid + i * NTHREADS;
                        const uint32_t d = dstB + (uint32_t)(idx >> 3) * (BSTRIDE * 2) + (idx & 7) * 16;
                        cp16(d, src + idx * 16);
                    }
                }
                CP_COMMIT();                       // uniform group count
                cg++;
            }

            // ---- epilogue: relu(acc+bias) -> fp16, in place (post-gemm barrier passed) ----
            {
                uint32_t* aW = (uint32_t*)(sm + A_PL);
                const float* bb = Bp[layer];
#pragma unroll
                for (int idx = 0; idx < 16; idx++) {
                    const int ms = idx >> 2, nf = idx & 3;
                    const int row = rowBase + 16 * ms;
                    const int col = colBase + 8 * nf;
                    const float2 bv = __ldg((const float2*)(bb + col));
                    const float h00 = fmaxf(acc[idx][0] + bv.x, 0.f);
                    const float h01 = fmaxf(acc[idx][1] + bv.y, 0.f);
                    const float h10 = fmaxf(acc[idx][2] + bv.x, 0.f);
                    const float h11 = fmaxf(acc[idx][3] + bv.y, 0.f);
                    aW[row * (ASTRIDE/2) + (col >> 1)]       = pack_h2(h00, h01);
                    aW[(row + 8) * (ASTRIDE/2) + (col >> 1)] = pack_h2(h10, h11);
                }
            }
            __syncthreads();
        }

        // ---- final 256 -> n4 dot: 2 threads per sample (fp16 hidden in A plane) ----
        if (tid < 2 * MH) {
            const int m = tid >> 1, hf = tid & 1;
            float o5[5];
            const float* b4 = Bp[4];
#pragma unroll
            for (int j = 0; j < 5; j++) o5[j] = (hf == 0 && j < n4) ? __ldg(b4 + j) : 0.f;
            const char* arow = sm + A_PL + (size_t)(m * ASTRIDE + hf * 128) * 2;
            for (int kk = 0; kk < 16; kk++) {
                const uint4 v = *(const uint4*)(arow + kk * 16);
                const float2 f0 = h2f(v.x), f1 = h2f(v.y), f2 = h2f(v.z), f3 = h2f(v.w);
                const float* w = sW4f + (hf * 128 + kk * 8) * n4;
#pragma unroll
                for (int j = 0; j < 5; j++) {
                    if (j < n4) {
                        o5[j] += f0.x * w[0*n4+j] + f0.y * w[1*n4+j]
                               + f1.x * w[2*n4+j] + f1.y * w[3*n4+j]
                               + f2.x * w[4*n4+j] + f2.y * w[5*n4+j]
                               + f3.x * w[6*n4+j] + f3.y * w[7*n4+j];
                    }
                }
            }
#pragma unroll
            for (int j = 0; j < 5; j++) o5[j] += __shfl_xor_sync(0xffffffffu, o5[j], 1);
            if (hf == 0) {
                if (mlp == 0) {
                    sOutS[m*4+0] = o5[0]; sOutS[m*4+1] = o5[1];
                    sOutS[m*4+2] = o5[2]; sOutS[m*4+3] = o5[3];
                } else {
                    const long sidx = (long)ray * SS + s0 + m;
                    const float bw = sigmoidf_(o5[4]);
                    g_sig[sidx] = (1.f - bw) * sOutS[m*4+0] + bw * o5[0];
                    g_bw[sidx]  = bw;
#pragma unroll
                    for (int cc = 0; cc < 3; cc++) {
                        const float rs = sigmoidf_(sOutS[m*4+1+cc]);
                        const float rd = sigmoidf_(o5[1+cc]);
                        g_rgb[sidx*3+cc] = (1.f - bw) * rs + bw * rd;
                    }
                }
            }
        }
        __syncthreads();
    }
}

// ---------------- kernel 2: per-ray compositing (one warp per ray) ----------------
__global__ void __launch_bounds__(32, 16)
nerf_compose(const float* __restrict__ zv, float* __restrict__ out, int R)
{
    const int ray  = blockIdx.x;
    const int lane = threadIdx.x;
    const long rb = (long)ray * SS;

    float zr[4], a[4], o[4], bwv[4], rg[4][3];
#pragma unroll
    for (int j = 0; j < 4; j++) {
        const int m = 4 * lane + j;
        zr[j]  = zv[rb + m];
        bwv[j] = g_bw[rb + m];
        rg[j][0] = g_rgb[(rb+m)*3+0]; rg[j][1] = g_rgb[(rb+m)*3+1]; rg[j][2] = g_rgb[(rb+m)*3+2];
    }
    const float znext = __shfl_down_sync(0xffffffffu, zr[0], 1);
#pragma unroll
    for (int j = 0; j < 4; j++) {
        float delta;
        if (j < 3)            delta = zr[j+1] - zr[j];
        else if (lane < 31)   delta = znext - zr[3];
        else                  delta = 1e10f;
        const float alpha = 1.f - expf(-g_sig[rb + 4*lane + j] * delta);
        a[j] = alpha;
        o[j] = 1.f - alpha + 1e-10f;
    }
    float run = o[0] * o[1] * o[2] * o[3];
#pragma unroll
    for (int d = 1; d < 32; d <<= 1) {
        const float v = __shfl_up_sync(0xffffffffu, run, d);
        if (lane >= d) run *= v;
    }
    float T = __shfl_up_sync(0xffffffffu, run, 1);
    if (lane == 0) T = 1.f;
    float r0 = 0.f, r1 = 0.f, r2 = 0.f, dep = 0.f;
    const long base = (long)R * 4;
    const long rs = (long)R * SS;
#pragma unroll
    for (int j = 0; j < 4; j++) {
        const float w = a[j] * T;
        const long oidx = rb + 4*lane + j;
        out[base + oidx]          = w;
        out[base + rs + oidx]     = (1.f - bwv[j]) * w;
        out[base + 2 * rs + oidx] = bwv[j] * w;
        r0 += w * rg[j][0]; r1 += w * rg[j][1]; r2 += w * rg[j][2];
        dep += w * zr[j];
        T *= o[j];
    }
#pragma unroll
    for (int d = 16; d > 0; d >>= 1) {
        r0  += __shfl_xor_sync(0xffffffffu, r0, d);
        r1  += __shfl_xor_sync(0xffffffffu, r1, d);
        r2  += __shfl_xor_sync(0xffffffffu, r2, d);
        dep += __shfl_xor_sync(0xffffffffu, dep, d);
    }
    if (lane == 0) {
        out[ray*3+0] = r0; out[ray*3+1] = r1; out[ray*3+2] = r2;
        out[(long)R * 3 + ray] = dep;
    }
}

extern "C" void kernel_launch(void* const* d_in, const int* in_sizes, int n_in,
                              void* d_out, int out_size)
{
    const float* pts = (const float*)d_in[0];
    const float* dir = (const float*)d_in[1];
    const float* zv  = (const float*)d_in[2];
    const float* tim = (const float*)d_in[3];

    MLPParams st, dy;
    for (int i = 0; i < 5; i++) {
        st.W[i] = (const float*)d_in[4 + 4 * i];
        st.b[i] = (const float*)d_in[5 + 4 * i];
        dy.W[i] = (const float*)d_in[6 + 4 * i];
        dy.b[i] = (const float*)d_in[7 + 4 * i];
    }

    const int R = in_sizes[2] / SS;

    prepass_kernel<<<2 * NCHUNK, 256>>>(st, dy);

    cudaFuncSetAttribute(nerf_mlp, cudaFuncAttributeMaxDynamicSharedMemorySize, SM_TOTAL);
    nerf_mlp<<<2 * R, NTHREADS, SM_TOTAL>>>(pts, dir, tim, st, dy);

    nerf_compose<<<R, 32>>>(zv, (float*)d_out, R);
}

// round 17
// speedup vs baseline: 1.0745x; 1.0745x over previous
#include <cuda_runtime.h>
#include <cuda_fp16.h>
#include <math.h>
#include <stdint.h>

// ---------------- problem constants ----------------
#define SS        128
#define HID       256
#define NTHREADS  512
#define KC        64               // K per weight chunk (fp16)
#define NCHUNK    14               // per MLP: layer0: 2 (Kpad=128), layers1-3: 4 each
#define ASTRIDE   264              // A plane row stride in fp16 (33*16B: conflict-free ldmatrix)
#define BSTRIDE   72               // B row stride fp16 (9*16B: odd -> conflict-free)
#define BSLICE    4608             // one pair slice buffer: 32 rows * 144 B
#define PLANE     67584            // one A plane: 128*264*2

// ---- shared memory byte offsets ----
#define A_P0      0                              // plane 0
#define A_P1      67584                          // plane 1
#define BUFBASE   135168                         // 8 pairs * 2 * 4608 = 73728 -> 208896
#define SM_W4     208896                         // 256*5*4 = 5120 -> 214016
#define SM_OUTS   214016                         // 2048 -> 216064 (reused alpha/oma)
#define SM_SIG    216064
#define SM_BW     216576
#define SM_RGB    217088                         // 1536 -> 218624
#define SM_Z      218624
#define SM_WGT    219136
#define SM_TOTAL  219648

// Pre-transposed fp16 weight slices: [mlp][chunk][pair][32*64]
__device__ __align__(16) __half g_wimg[2][NCHUNK][8][32 * KC];

struct MLPParams { const float* W[5]; const float* b[5]; };

// ---------------- PTX helpers (all baseline sm_80 ISA) ----------------
__device__ __forceinline__ uint32_t smem_u32(const void* p) {
    uint32_t a;
    asm("{ .reg .u64 t; cvta.to.shared.u64 t, %1; cvt.u32.u64 %0, t; }" : "=r"(a) : "l"(p));
    return a;
}

#define LDSM4(r0, r1, r2, r3, addr) \
    asm volatile("ldmatrix.sync.aligned.m8n8.x4.shared.b16 {%0,%1,%2,%3}, [%4];" \
        : "=r"(r0), "=r"(r1), "=r"(r2), "=r"(r3) : "r"(addr))

#define MMA16816(c, a0, a1, a2, a3, b0, b1) \
    asm volatile("mma.sync.aligned.m16n8k16.row.col.f32.f16.f16.f32 " \
        "{%0,%1,%2,%3}, {%4,%5,%6,%7}, {%8,%9}, {%0,%1,%2,%3};" \
        : "+f"((c)[0]), "+f"((c)[1]), "+f"((c)[2]), "+f"((c)[3]) \
        : "r"(a0), "r"(a1), "r"(a2), "r"(a3), "r"(b0), "r"(b1))

__device__ __forceinline__ void cp16(uint32_t dst, const void* src) {
    asm volatile("cp.async.cg.shared.global [%0], [%1], 16;" :: "r"(dst), "l"(src));
}
#define CP_COMMIT() asm volatile("cp.async.commit_group;" ::: "memory")
#define CP_WAIT1()  asm volatile("cp.async.wait_group 1;" ::: "memory")
#define CP_WAIT0()  asm volatile("cp.async.wait_group 0;" ::: "memory")
#define PBAR(id)    asm volatile("bar.sync %0, 64;" :: "r"(id) : "memory")

__device__ __forceinline__ float sigmoidf_(float x) { return 1.0f / (1.0f + expf(-x)); }

__device__ __forceinline__ uint32_t pack_h2(float v0, float v1) {
    __half2 h = __floats2half2_rn(v0, v1);
    return *reinterpret_cast<uint32_t*>(&h);
}
__device__ __forceinline__ float2 h2f(uint32_t u) {
    __half2 h = *reinterpret_cast<__half2*>(&u);
    return __half22float2(h);
}

// ---------------- pre-pass: [pair][32 rows][Kc=64] fp16 slices ----------------
__global__ void prepass_kernel(MLPParams st, MLPParams dy) {
    const int bi  = blockIdx.x;            // 0..27
    const int mlp = bi / NCHUNK;
    const int c   = bi % NCHUNK;
    const int layer = (c < 2) ? 0 : 1 + (c - 2) / 4;
    const int kbase = (c < 2) ? c * KC : ((c - 2) % 4) * KC;
    const float* W = mlp ? dy.W[layer] : st.W[layer];
    const int Kreal = (layer == 0) ? (mlp ? 99 : 90) : HID;

    const int n = threadIdx.x;             // 0..255 global N
    __half* outH = g_wimg[mlp][c][n >> 5] + (n & 31) * KC;
    for (int k = 0; k < KC; k++) {
        const int kg = kbase + k;
        const float w = (kg < Kreal) ? __ldg(W + (size_t)kg * HID + n) : 0.f;
        outH[k] = __float2half_rn(w);
    }
}

// ---- GEMM chunk: warp tile 64(M) x 32(N), Kc=64, LDS/MMA interleaved ----
// acc index: ms*4 + ns*2 + {0,1}
__device__ __forceinline__ void gemm_chunk(uint32_t aBase, uint32_t bB, float acc[16][4]) {
    uint32_t a[16], b[2][8];
#pragma unroll
    for (int ms = 0; ms < 4; ms++)
        LDSM4(a[ms*4+0], a[ms*4+1], a[ms*4+2], a[ms*4+3],
              aBase + ms * (16 * ASTRIDE * 2));
#pragma unroll
    for (int ns = 0; ns < 2; ns++)
        LDSM4(b[0][ns*4+0], b[0][ns*4+1], b[0][ns*4+2], b[0][ns*4+3],
              bB + ns * (16 * BSTRIDE * 2));
#pragma unroll
    for (int ks = 0; ks < 4; ks++) {
        const int cur = ks & 1, nxt = cur ^ 1;
        if (ks < 3) {
            const uint32_t nbk = bB + (ks + 1) * 32;
#pragma unroll
            for (int ns = 0; ns < 2; ns++)
                LDSM4(b[nxt][ns*4+0], b[nxt][ns*4+1], b[nxt][ns*4+2], b[nxt][ns*4+3],
                      nbk + ns * (16 * BSTRIDE * 2));
        }
#pragma unroll
        for (int ms = 0; ms < 4; ms++) {
            MMA16816(acc[ms*4+0], a[ms*4+0], a[ms*4+1], a[ms*4+2], a[ms*4+3],
                     b[cur][0], b[cur][1]);
            MMA16816(acc[ms*4+1], a[ms*4+0], a[ms*4+1], a[ms*4+2], a[ms*4+3],
                     b[cur][2], b[cur][3]);
            MMA16816(acc[ms*4+2], a[ms*4+0], a[ms*4+1], a[ms*4+2], a[ms*4+3],
                     b[cur][4], b[cur][5]);
            MMA16816(acc[ms*4+3], a[ms*4+0], a[ms*4+1], a[ms*4+2], a[ms*4+3],
                     b[cur][6], b[cur][7]);
            if (ks < 3)
                LDSM4(a[ms*4+0], a[ms*4+1], a[ms*4+2], a[ms*4+3],
                      aBase + (ks + 1) * 32 + ms * (16 * ASTRIDE * 2));
        }
    }
}

// ---------------- main kernel ----------------
__global__ void __launch_bounds__(NTHREADS, 1)
nerf_main(const float* __restrict__ pts, const float* __restrict__ dir,
          const float* __restrict__ zv,  const float* __restrict__ tim,
          MLPParams st, MLPParams dy, float* __restrict__ out, int R)
{
    extern __shared__ char sm[];
    const uint32_t sbase = smem_u32(sm);

    const int tid  = threadIdx.x;
    const int wid  = tid >> 5;
    const int lane = tid & 31;
    const int ray  = blockIdx.x;

    const int pr   = wid >> 1;           // pair 0..7 -> N cols 32*pr
    const int mi   = wid & 1;            // 0,1 -> rows 64*mi
    const int gt64 = tid & 63;           // index within pair
    const uint32_t myBufBase = sbase + BUFBASE + (uint32_t)pr * (2 * BSLICE);

    float* sZ    = (float*)(sm + SM_Z);
    float* sWgt  = (float*)(sm + SM_WGT);
    float* sSig  = (float*)(sm + SM_SIG);
    float* sBW   = (float*)(sm + SM_BW);
    float* sRgb  = (float*)(sm + SM_RGB);
    float* sOutS = (float*)(sm + SM_OUTS);
    float* sW4f  = (float*)(sm + SM_W4);

    if (tid < SS) sZ[tid] = zv[(long)ray * SS + tid];

    // per-thread ldmatrix address components
    const int r8 = lane & 7, g = lane >> 3;
    const uint32_t aRow = (uint32_t)(64 * mi + (g & 1) * 8 + r8);
    const uint32_t aOffBase = (aRow * ASTRIDE + (uint32_t)(g >> 1) * 8) * 2;
    const uint32_t bRow = (uint32_t)((g >> 1) * 8 + r8);          // local row in 32-row slice
    const uint32_t bOff = (bRow * BSTRIDE + (g & 1) * 8) * 2;

    const int rowBase = 64 * mi + (lane >> 2);       // + 16*ms, +8 for c[2..3]
    const int colBase = pr * 32 + 2 * (lane & 3);    // + 8*nf

    for (int mlp = 0; mlp < 2; mlp++) {
        const float* const* Wp = mlp ? dy.W : st.W;
        const float* const* Bp = mlp ? dy.b : st.b;
        const int n4 = mlp ? 5 : 4;

        CP_WAIT0();
        __syncthreads();       // prior-phase smem reuse safe

        // ---- encode directly into fp16 plane 0, 4-way warp-uniform split ----
        {
            const int m = tid & 127;
            const int q = tid >> 7;
            const long base = (long)ray * SS + m;
            char* arow = sm + A_P0 + (size_t)m * (ASTRIDE * 2);
#define STH(col, v) (*(__half*)(arow + (col) * 2) = __float2half_rn(v))
            if (q == 0) {
                const float p0 = pts[base*3+0], p1 = pts[base*3+1], p2 = pts[base*3+2];
                STH(0, p0); STH(1, p1); STH(2, p2);
                float f = 1.f;
#pragma unroll
                for (int l = 0; l < 5; l++) {
                    float c0,sx,c1,sy,c2,sz;
                    sincosf(f*p0,&sx,&c0); sincosf(f*p1,&sy,&c1); sincosf(f*p2,&sz,&c2);
                    const int o = 3 + 6*l;
                    STH(o,sx); STH(o+1,sy); STH(o+2,sz);
                    STH(o+3,c0); STH(o+4,c1); STH(o+5,c2);
                    f *= 2.f;
                }
            } else if (q == 1) {
                const float p0 = pts[base*3+0], p1 = pts[base*3+1], p2 = pts[base*3+2];
                float f = 32.f;
#pragma unroll
                for (int l = 0; l < 5; l++) {
                    float c0,sx,c1,sy,c2,sz;
                    sincosf(f*p0,&sx,&c0); sincosf(f*p1,&sy,&c1); sincosf(f*p2,&sz,&c2);
                    const int o = 33 + 6*l;
                    STH(o,sx); STH(o+1,sy); STH(o+2,sz);
                    STH(o+3,c0); STH(o+4,c1); STH(o+5,c2);
                    f *= 2.f;
                }
            } else if (q == 2) {
                const float d0 = dir[base*3+0], d1 = dir[base*3+1], d2 = dir[base*3+2];
                STH(63, d0); STH(64, d1); STH(65, d2);
                float f = 1.f;
#pragma unroll
                for (int l = 0; l < 4; l++) {
                    float c0,sx,c1,sy,c2,sz;
                    sincosf(f*d0,&sx,&c0); sincosf(f*d1,&sy,&c1); sincosf(f*d2,&sz,&c2);
                    const int o = 66 + 6*l;
                    STH(o,sx); STH(o+1,sy); STH(o+2,sz);
                    STH(o+3,c0); STH(o+4,c1); STH(o+5,c2);
                    f *= 2.f;
                }
            } else {
                const float t = tim[base];
                STH(90, t);
                float f = 1.f;
#pragma unroll
                for (int l = 0; l < 4; l++) {
                    float s, c; sincosf(f*t, &s, &c);
                    STH(91 + 2*l, s); STH(92 + 2*l, c);
                    f *= 2.f;
                }
#pragma unroll
                for (int col = 99; col < 128; col++) STH(col, 0.f);
            }
#undef STH
        }
        __syncthreads();

        // ---- per-pair prefetch of chunks 0,1 (256 x 16B per slice; pads unused) ----
        int cg = 0;
        for (int pc = 0; pc < 2; pc++) {
            const char* src = (const char*)g_wimg[mlp][pc][pr];
            const uint32_t dstB = myBufBase + (uint32_t)pc * BSLICE;
#pragma unroll
            for (int i = 0; i < 4; i++) {
                const int idx = gt64 + i * 64;                   // 0..255
                const uint32_t d = dstB + (uint32_t)(idx >> 3) * (BSTRIDE * 2) + (idx & 7) * 16;
                cp16(d, src + idx * 16);
            }
            CP_COMMIT();
        }

        for (int layer = 0; layer < 4; layer++) {
            const uint32_t rPlane = sbase + (uint32_t)(layer & 1) * PLANE;   // read plane
            if (layer == 3)
                for (int i = tid; i < HID * n4; i += NTHREADS) sW4f[i] = __ldg(Wp[4] + i);

            float acc[16][4];
#pragma unroll
            for (int a = 0; a < 16; a++)
#pragma unroll
                for (int q = 0; q < 4; q++) acc[a][q] = 0.f;

            const int nch = (layer == 0) ? 2 : 4;
            for (int c = 0; c < nch; c++) {
                CP_WAIT1();                        // own share of chunk cg landed
                PBAR(1 + pr);                      // partner's share visible (pair-local)
                const uint32_t bB = myBufBase + (uint32_t)(cg & 1) * BSLICE + bOff;
                gemm_chunk(rPlane + aOffBase + c * (KC * 2), bB, acc);
                PBAR(1 + pr);                      // pair done reading buf (cg&1)
                if (cg + 2 < NCHUNK) {
                    const char* src = (const char*)g_wimg[mlp][cg + 2][pr];
                    const uint32_t dstB = myBufBase + (uint32_t)(cg & 1) * BSLICE;
#pragma unroll
                    for (int i = 0; i < 4; i++) {
                        const int idx = gt64 + i * 64;
                        const uint32_t d = dstB + (uint32_t)(idx >> 3) * (BSTRIDE * 2) + (idx & 7) * 16;
                        cp16(d, src + idx * 16);
                    }
                }
                CP_COMMIT();                       // uniform group count
                cg++;
            }

            // ---- epilogue: relu(acc+bias) -> fp16 into PONG plane (no barrier needed) ----
            {
                uint32_t* aW = (uint32_t*)(sm + (((layer & 1) ^ 1) ? A_P1 : A_P0));
                const float* bb = Bp[layer];
#pragma unroll
                for (int idx = 0; idx < 16; idx++) {
                    const int ms = idx >> 2, nf = idx & 3;
                    const int row = rowBase + 16 * ms;
                    const int col = colBase + 8 * nf;
                    const float2 bv = __ldg((const float2*)(bb + col));
                    const float h00 = fmaxf(acc[idx][0] + bv.x, 0.f);
                    const float h01 = fmaxf(acc[idx][1] + bv.y, 0.f);
                    const float h10 = fmaxf(acc[idx][2] + bv.x, 0.f);
                    const float h11 = fmaxf(acc[idx][3] + bv.y, 0.f);
                    aW[row * (ASTRIDE/2) + (col >> 1)]       = pack_h2(h00, h01);
                    aW[(row + 8) * (ASTRIDE/2) + (col >> 1)] = pack_h2(h10, h11);
                }
            }
            __syncthreads();   // all of next layer's A written before anyone reads it
        }

        // ---- final 256 -> n4 dot: 2 threads per sample (fp16 hidden in plane 0) ----
        if (tid < 2 * SS) {
            const int m = tid >> 1, hf = tid & 1;
            float o5[5];
            const float* b4 = Bp[4];
#pragma unroll
            for (int j = 0; j < 5; j++) o5[j] = (hf == 0 && j < n4) ? __ldg(b4 + j) : 0.f;
            const char* arow = sm + A_P0 + (size_t)(m * ASTRIDE + hf * 128) * 2;
            for (int kk = 0; kk < 16; kk++) {
                const uint4 v = *(const uint4*)(arow + kk * 16);
                const float2 f0 = h2f(v.x), f1 = h2f(v.y), f2 = h2f(v.z), f3 = h2f(v.w);
                const float* w = sW4f + (hf * 128 + kk * 8) * n4;
#pragma unroll
                for (int j = 0; j < 5; j++) {
                    if (j < n4) {
                        o5[j] += f0.x * w[0*n4+j] + f0.y * w[1*n4+j]
                               + f1.x * w[2*n4+j] + f1.y * w[3*n4+j]
                               + f2.x * w[4*n4+j] + f2.y * w[5*n4+j]
                               + f3.x * w[6*n4+j] + f3.y * w[7*n4+j];
                    }
                }
            }
#pragma unroll
            for (int j = 0; j < 5; j++) o5[j] += __shfl_xor_sync(0xffffffffu, o5[j], 1);
            if (hf == 0) {
                if (mlp == 0) {
                    sOutS[m*4+0] = o5[0]; sOutS[m*4+1] = o5[1];
                    sOutS[m*4+2] = o5[2]; sOutS[m*4+3] = o5[3];
                } else {
                    const float bw = sigmoidf_(o5[4]);
                    sSig[m] = (1.f - bw) * sOutS[m*4+0] + bw * o5[0];
                    sBW[m]  = bw;
#pragma unroll
                    for (int cc = 0; cc < 3; cc++) {
                        const float rs = sigmoidf_(sOutS[m*4+1+cc]);
                        const float rd = sigmoidf_(o5[1+cc]);
                        sRgb[m*3+cc] = (1.f - bw) * rs + bw * rd;
                    }
                }
            }
        }
        __syncthreads();
    }

    // ---- parallel alpha, then warp-0 prefix-product scan + reductions ----
    float* sAlpha = sOutS;            // reuse (sOutS dead now)
    float* sOma   = sOutS + SS;
    if (tid < SS) {
        const float z = sZ[tid];
        const float delta = (tid < SS - 1) ? (sZ[tid + 1] - z) : 1e10f;
        const float alpha = 1.f - expf(-sSig[tid] * delta);
        sAlpha[tid] = alpha;
        sOma[tid]   = 1.f - alpha + 1e-10f;
    }
    __syncthreads();
    if (wid == 0) {
        float a[4], o[4], zr[4], rg[4][3];
#pragma unroll
        for (int j = 0; j < 4; j++) {
            const int m = 4 * lane + j;
            a[j] = sAlpha[m]; o[j] = sOma[m]; zr[j] = sZ[m];
            rg[j][0] = sRgb[m*3+0]; rg[j][1] = sRgb[m*3+1]; rg[j][2] = sRgb[m*3+2];
        }
        float run = o[0] * o[1] * o[2] * o[3];
#pragma unroll
        for (int d = 1; d < 32; d <<= 1) {
            const float v = __shfl_up_sync(0xffffffffu, run, d);
            if (lane >= d) run *= v;
        }
        float T = __shfl_up_sync(0xffffffffu, run, 1);
        if (lane == 0) T = 1.f;
        float r0 = 0.f, r1 = 0.f, r2 = 0.f, dep = 0.f;
#pragma unroll
        for (int j = 0; j < 4; j++) {
            const float w = a[j] * T;
            sWgt[4 * lane + j] = w;
            r0 += w * rg[j][0]; r1 += w * rg[j][1]; r2 += w * rg[j][2];
            dep += w * zr[j];
            T *= o[j];
        }
#pragma unroll
        for (int d = 16; d > 0; d >>= 1) {
            r0  += __shfl_xor_sync(0xffffffffu, r0, d);
            r1  += __shfl_xor_sync(0xffffffffu, r1, d);
            r2  += __shfl_xor_sync(0xffffffffu, r2, d);
            dep += __shfl_xor_sync(0xffffffffu, dep, d);
        }
        if (lane == 0) {
            out[ray*3+0] = r0; out[ray*3+1] = r1; out[ray*3+2] = r2;
            out[(long)R * 3 + ray] = dep;
        }
    }
    __syncthreads();

    if (tid < SS) {
        const int m = tid;
        const float w  = sWgt[m];
        const float bw = sBW[m];
        const long o = (long)ray * SS + m;
        const long base = (long)R * 4;
        const long rs = (long)R * SS;
        out[base + o]          = w;
        out[base + rs + o]     = (1.f - bw) * w;
        out[base + 2 * rs + o] = bw * w;
    }
}

extern "C" void kernel_launch(void* const* d_in, const int* in_sizes, int n_in,
                              void* d_out, int out_size)
{
    const float* pts = (const float*)d_in[0];
    const float* dir = (const float*)d_in[1];
    const float* zv  = (const float*)d_in[2];
    const float* tim = (const float*)d_in[3];

    MLPParams st, dy;
    for (int i = 0; i < 5; i++) {
        st.W[i] = (const float*)d_in[4 + 4 * i];
        st.b[i] = (const float*)d_in[5 + 4 * i];
        dy.W[i] = (const float*)d_in[6 + 4 * i];
        dy.b[i] = (const float*)d_in[7 + 4 * i];
    }

    const int R = in_sizes[2] / SS;

    prepass_kernel<<<2 * NCHUNK, 256>>>(st, dy);

    cudaFuncSetAttribute(nerf_main, cudaFuncAttributeMaxDynamicSharedMemorySize, SM_TOTAL);
    nerf_main<<<R, NTHREADS, SM_TOTAL>>>(pts, dir, zv, tim, st, dy, (float*)d_out, R);
}